// round 11
// baseline (speedup 1.0000x reference)
#include <cuda_runtime.h>
#include <cstdint>

// Instant-NGP hash grid: D=3, L=16, C=2, H=16, MAX_PARAMS=2^19
// Levels 0..2 dense ((res+1)^3 entries), levels 3..15 hashed (2^19 entries).
#define NB 524288u          // points
#define HASH_MASK 0x7FFFFu  // 2^19 - 1

__constant__ unsigned c_level_off[16] = {
    0u,       4913u,    40850u,   315475u,
    839763u,  1364051u, 1888339u, 2412627u,
    2936915u, 3461203u, 3985491u, 4509779u,
    5034067u, 5558355u, 6082643u, 6606931u
};

__global__ __launch_bounds__(256)
void hash_encode_kernel(const float* __restrict__ xin,
                        const float* __restrict__ emb,
                        float* __restrict__ out)
{
    unsigned tid = blockIdx.x * blockDim.x + threadIdx.x;  // exact grid
    unsigned b = tid >> 4;      // point
    unsigned l = tid & 15u;     // level

    // map [-1,1] -> [0,1] (matches reference: (x+1)/2)
    float px = (__ldg(xin + 3u * b + 0u) + 1.0f) * 0.5f;
    float py = (__ldg(xin + 3u * b + 1u) + 1.0f) * 0.5f;
    float pz = (__ldg(xin + 3u * b + 2u) + 1.0f) * 0.5f;

    unsigned res = 16u << l;
    float fres = (float)res;
    float posx = px * fres, posy = py * fres, posz = pz * fres;
    float gx = floorf(posx), gy = floorf(posy), gz = floorf(posz);
    float fx = posx - gx, fy = posy - gy, fz = posz - gz;
    unsigned ix = (unsigned)gx, iy = (unsigned)gy, iz = (unsigned)gz;

    unsigned off = c_level_off[l];
    // global entry indices for the 8 corners (corner bit0 = x, bit1 = y, bit2 = z)
    unsigned g0, g1, g2, g3, g4, g5, g6, g7;
    if (l < 3u) {
        unsigned r1 = res + 1u;
        unsigned s2 = r1 * r1;
        unsigned base = off + ix + iy * r1 + iz * s2;
        g0 = base;
        g1 = base + 1u;
        g2 = base + r1;
        g3 = base + r1 + 1u;
        g4 = base + s2;
        g5 = base + s2 + 1u;
        g6 = base + s2 + r1;
        g7 = base + s2 + r1 + 1u;
    } else {
        unsigned hx0 = ix,               hx1 = ix + 1u;
        unsigned hy0 = iy * 2654435761u, hy1 = (iy + 1u) * 2654435761u;
        unsigned hz0 = iz * 805459861u,  hz1 = (iz + 1u) * 805459861u;
        g0 = ((hx0 ^ hy0 ^ hz0) & HASH_MASK) + off;
        g1 = ((hx1 ^ hy0 ^ hz0) & HASH_MASK) + off;
        g2 = ((hx0 ^ hy1 ^ hz0) & HASH_MASK) + off;
        g3 = ((hx1 ^ hy1 ^ hz0) & HASH_MASK) + off;
        g4 = ((hx0 ^ hy0 ^ hz1) & HASH_MASK) + off;
        g5 = ((hx1 ^ hy0 ^ hz1) & HASH_MASK) + off;
        g6 = ((hx0 ^ hy1 ^ hz1) & HASH_MASK) + off;
        g7 = ((hx1 ^ hy1 ^ hz1) & HASH_MASK) + off;
    }

    // Table viewed as aligned 16B blocks of two float2 entries.
    const float4* __restrict__ f4 = reinterpret_cast<const float4*>(emb);

    // x-pairs: (g0,g1) (g2,g3) (g4,g5) (g6,g7).
    // If (ga ^ gb) == 1 the pair shares one aligned block -> single LDG.128.
    bool n0 = (g0 ^ g1) != 1u;
    bool n1 = (g2 ^ g3) != 1u;
    bool n2 = (g4 ^ g5) != 1u;
    bool n3 = (g6 ^ g7) != 1u;

    // all loads issued front-to-back: 4 unconditional + 4 predicated LDG.128
    float4 A0 = __ldg(f4 + (g0 >> 1));
    float4 A1 = __ldg(f4 + (g2 >> 1));
    float4 A2 = __ldg(f4 + (g4 >> 1));
    float4 A3 = __ldg(f4 + (g6 >> 1));
    float4 B0, B1, B2, B3;
    if (n0) B0 = __ldg(f4 + (g1 >> 1));
    if (n1) B1 = __ldg(f4 + (g3 >> 1));
    if (n2) B2 = __ldg(f4 + (g5 >> 1));
    if (n3) B3 = __ldg(f4 + (g7 >> 1));

    // trilinear weights (computed while loads are in flight)
    float gxc = 1.0f - fx, gyc = 1.0f - fy, gzc = 1.0f - fz;
    float w0 = gxc * gyc * gzc;
    float w1 = fx  * gyc * gzc;
    float w2 = gxc * fy  * gzc;
    float w3 = fx  * fy  * gzc;
    float w4 = gxc * gyc * fz;
    float w5 = fx  * gyc * fz;
    float w6 = gxc * fy  * fz;
    float w7 = fx  * fy  * fz;

    if (!n0) B0 = A0;
    if (!n1) B1 = A1;
    if (!n2) B2 = A2;
    if (!n3) B3 = A3;

    // select the correct half of each block per corner parity
    float v0x = (g0 & 1u) ? A0.z : A0.x,  v0y = (g0 & 1u) ? A0.w : A0.y;
    float v1x = (g1 & 1u) ? B0.z : B0.x,  v1y = (g1 & 1u) ? B0.w : B0.y;
    float v2x = (g2 & 1u) ? A1.z : A1.x,  v2y = (g2 & 1u) ? A1.w : A1.y;
    float v3x = (g3 & 1u) ? B1.z : B1.x,  v3y = (g3 & 1u) ? B1.w : B1.y;
    float v4x = (g4 & 1u) ? A2.z : A2.x,  v4y = (g4 & 1u) ? A2.w : A2.y;
    float v5x = (g5 & 1u) ? B2.z : B2.x,  v5y = (g5 & 1u) ? B2.w : B2.y;
    float v6x = (g6 & 1u) ? A3.z : A3.x,  v6y = (g6 & 1u) ? A3.w : A3.y;
    float v7x = (g7 & 1u) ? B3.z : B3.x,  v7y = (g7 & 1u) ? B3.w : B3.y;

    float ox = w0 * v0x + w1 * v1x + w2 * v2x + w3 * v3x
             + w4 * v4x + w5 * v5x + w6 * v6x + w7 * v7x;
    float oy = w0 * v0y + w1 * v1y + w2 * v2y + w3 * v3y
             + w4 * v4y + w5 * v5y + w6 * v6y + w7 * v7y;

    reinterpret_cast<float2*>(out)[b * 16u + l] = make_float2(ox, oy);
}

extern "C" void kernel_launch(void* const* d_in, const int* in_sizes, int n_in,
                              void* d_out, int out_size)
{
    const float* xin = (const float*)d_in[0];   // inputs  [B, 3]
    const float* emb = (const float*)d_in[1];   // embeddings [7131219, 2]
    float* out = (float*)d_out;                 // [B, 32] float

    unsigned total = NB * 16u;                  // 8388608 threads
    hash_encode_kernel<<<total / 256u, 256u>>>(xin, emb, out);
}